// round 2
// baseline (speedup 1.0000x reference)
#include <cuda_runtime.h>
#include <float.h>
#include <math.h>

// Problem constants
#define BATCH  32
#define SEQ    577
#define DMODEL 768
#define NHEAD  12
#define HDIM   64
#define MROWS  (BATCH * SEQ)            // 18464
#define ELEMS  (BATCH * NHEAD * SEQ * HDIM)  // 14,180,352 == MROWS*DMODEL

// Scratch (static device globals: allocation-free, graph-capture safe)
__device__ float g_Q[ELEMS];    // [B, H, N, 64]
__device__ float g_K[ELEMS];    // [B, H, N, 64]
__device__ float g_V[ELEMS];    // [B, H, N, 64]
__device__ float g_ctx[ELEMS];  // [B*N, 768] attention output pre-projection

// ---------------------------------------------------------------------------
// NT SGEMM: out[m, j] = sum_d A[m,d] * W[j,d] + bias[j]
// A: [MROWS, 768] row-major (K contiguous); W: [768, 768] row-major (K contiguous)
// mode 0/1/2: scatter into g_Q/g_K/g_V as [B,H,N,64]
// mode 3:     plain row-major store into outp; A==nullptr means A = g_ctx
// ---------------------------------------------------------------------------
#define BM 128
#define BN 128
#define BK 16
#define TM 8
#define TN 8

__global__ __launch_bounds__(256)
void gemm_nt(const float* __restrict__ A, const float* __restrict__ W,
             const float* __restrict__ bias, float* __restrict__ outp, int mode)
{
    __shared__ float As[BK][BM + 4];
    __shared__ float Bs[BK][BN + 4];

    const float* Asrc = A ? A : g_ctx;

    const int tid = threadIdx.x;
    const int block_m = blockIdx.y * BM;
    const int block_n = blockIdx.x * BN;
    const int trow = (tid >> 4) * TM;   // 0..120
    const int tcol = (tid & 15) * TN;   // 0..120

    float acc[TM][TN];
#pragma unroll
    for (int i = 0; i < TM; i++)
#pragma unroll
        for (int j = 0; j < TN; j++) acc[i][j] = 0.f;

    for (int k0 = 0; k0 < DMODEL; k0 += BK) {
        // Load A tile (BM x BK) transposed into As[k][m]; guard rows >= MROWS
#pragma unroll
        for (int i = 0; i < 2; i++) {
            int idx = tid + i * 256;          // 0..511
            int row = idx >> 2;               // 0..127
            int k4  = (idx & 3) << 2;         // 0,4,8,12
            int gm  = block_m + row;
            float4 v = make_float4(0.f, 0.f, 0.f, 0.f);
            if (gm < MROWS)
                v = *(const float4*)(Asrc + (size_t)gm * DMODEL + k0 + k4);
            As[k4 + 0][row] = v.x; As[k4 + 1][row] = v.y;
            As[k4 + 2][row] = v.z; As[k4 + 3][row] = v.w;
        }
        // Load W tile (BN x BK) transposed into Bs[k][n]; always in bounds (768x768)
#pragma unroll
        for (int i = 0; i < 2; i++) {
            int idx = tid + i * 256;
            int row = idx >> 2;
            int k4  = (idx & 3) << 2;
            float4 v = *(const float4*)(W + (size_t)(block_n + row) * DMODEL + k0 + k4);
            Bs[k4 + 0][row] = v.x; Bs[k4 + 1][row] = v.y;
            Bs[k4 + 2][row] = v.z; Bs[k4 + 3][row] = v.w;
        }
        __syncthreads();

#pragma unroll
        for (int kk = 0; kk < BK; kk++) {
            float a[TM], b[TN];
#pragma unroll
            for (int i = 0; i < TM; i++) a[i] = As[kk][trow + i];
#pragma unroll
            for (int j = 0; j < TN; j++) b[j] = Bs[kk][tcol + j];
#pragma unroll
            for (int i = 0; i < TM; i++)
#pragma unroll
                for (int j = 0; j < TN; j++) acc[i][j] += a[i] * b[j];
        }
        __syncthreads();
    }

    // Epilogue
    float* scatter_dst = (mode == 0) ? g_Q : (mode == 1) ? g_K : g_V;
#pragma unroll
    for (int i = 0; i < TM; i++) {
        int gm = block_m + trow + i;
        if (gm >= MROWS) continue;
        if (mode <= 2) {
            int b_idx = gm / SEQ;
            int n_idx = gm - b_idx * SEQ;
#pragma unroll
            for (int j = 0; j < TN; j++) {
                int gn = block_n + tcol + j;
                int h  = gn >> 6;
                int hd = gn & 63;
                float v = acc[i][j] + bias[gn];
                scatter_dst[(((size_t)b_idx * NHEAD + h) * SEQ + n_idx) * HDIM + hd] = v;
            }
        } else {
#pragma unroll
            for (int j = 0; j < TN; j++) {
                int gn = block_n + tcol + j;
                outp[(size_t)gm * DMODEL + gn] = acc[i][j] + bias[gn];
            }
        }
    }
}

// ---------------------------------------------------------------------------
// Flash-style attention with anti-causal mask (keys k >= q allowed),
// scale = 1/sqrt(768). One thread per query row; K/V tiles in smem.
// ---------------------------------------------------------------------------
#define QT 128
#define KT 32

__global__ __launch_bounds__(128)
void attn_kernel()
{
    __shared__ float Ks[KT][HDIM];
    __shared__ float Vs[KT][HDIM];

    const int bh  = blockIdx.y;                 // 0..383 = b*NHEAD + h
    const int q0  = blockIdx.x * QT;
    const int tid = threadIdx.x;
    const int q   = q0 + tid;
    const bool active = (q < SEQ);

    const float* Kbase = g_K + (size_t)bh * SEQ * HDIM;
    const float* Vbase = g_V + (size_t)bh * SEQ * HDIM;

    float qv[HDIM];
    if (active) {
        const float4* qp = (const float4*)(g_Q + (size_t)bh * SEQ * HDIM + (size_t)q * HDIM);
#pragma unroll
        for (int i = 0; i < HDIM / 4; i++) ((float4*)qv)[i] = qp[i];
    }

    float m = -FLT_MAX, l = 0.f;
    float acc[HDIM];
#pragma unroll
    for (int d = 0; d < HDIM; d++) acc[d] = 0.f;

    const float scale = 0.03608439182435161f;   // 1/sqrt(768)

    for (int kc = q0; kc < SEQ; kc += KT) {
        // Stage K/V tile (KT x 64) through smem; 512 float4 over 128 threads
#pragma unroll
        for (int i = 0; i < 4; i++) {
            int gidx = tid + i * 128;           // 0..511
            int row  = gidx >> 4;               // 0..31
            int c4   = (gidx & 15) << 2;        // 0..60
            int gk   = kc + row;
            float4 kv = make_float4(0.f, 0.f, 0.f, 0.f);
            float4 vv = make_float4(0.f, 0.f, 0.f, 0.f);
            if (gk < SEQ) {
                kv = *(const float4*)(Kbase + (size_t)gk * HDIM + c4);
                vv = *(const float4*)(Vbase + (size_t)gk * HDIM + c4);
            }
            *(float4*)&Ks[row][c4] = kv;
            *(float4*)&Vs[row][c4] = vv;
        }
        __syncthreads();

        // Tile is relevant iff it contains any key k >= q
        if (active && (kc + KT > q)) {
            float s[KT];
            float tmax = -FLT_MAX;
#pragma unroll
            for (int j = 0; j < KT; j++) {
                int k = kc + j;
                float dot = 0.f;
#pragma unroll
                for (int d = 0; d < HDIM; d++) dot += qv[d] * Ks[j][d];
                s[j] = (k < SEQ && k >= q) ? dot * scale : -FLT_MAX;
                tmax = fmaxf(tmax, s[j]);
            }
            // tmax is finite here: k == max(q, kc) < SEQ is always unmasked
            float mnew = fmaxf(m, tmax);
            float corr = __expf(m - mnew);      // 0 when m == -FLT_MAX
            l *= corr;
#pragma unroll
            for (int d = 0; d < HDIM; d++) acc[d] *= corr;
#pragma unroll
            for (int j = 0; j < KT; j++) {
                float p = __expf(s[j] - mnew);  // masked entries -> exp(-huge) = 0
                l += p;
#pragma unroll
                for (int d = 0; d < HDIM; d++) acc[d] += p * Vs[j][d];
            }
            m = mnew;
        }
        __syncthreads();
    }

    if (active) {
        float inv = 1.f / l;
        int b = bh / NHEAD, h = bh - b * NHEAD;
        float* op = g_ctx + ((size_t)(b * SEQ + q)) * DMODEL + h * HDIM;
#pragma unroll
        for (int i = 0; i < HDIM / 4; i++) {
            float4 o;
            o.x = acc[i * 4 + 0] * inv;
            o.y = acc[i * 4 + 1] * inv;
            o.z = acc[i * 4 + 2] * inv;
            o.w = acc[i * 4 + 3] * inv;
            ((float4*)op)[i] = o;
        }
    }
}

// ---------------------------------------------------------------------------
extern "C" void kernel_launch(void* const* d_in, const int* in_sizes, int n_in,
                              void* d_out, int out_size)
{
    (void)in_sizes; (void)n_in; (void)out_size;
    const float* x  = (const float*)d_in[0];
    const float* Wq = (const float*)d_in[1];
    const float* bq = (const float*)d_in[2];
    const float* Wk = (const float*)d_in[3];
    const float* bk = (const float*)d_in[4];
    const float* Wv = (const float*)d_in[5];
    const float* bv = (const float*)d_in[6];
    const float* Wo = (const float*)d_in[7];
    const float* bo = (const float*)d_in[8];
    float* out = (float*)d_out;

    dim3 gthreads(256);
    dim3 ggrid(DMODEL / BN, (MROWS + BM - 1) / BM);   // (6, 145)

    gemm_nt<<<ggrid, gthreads>>>(x, Wq, bq, nullptr, 0);
    gemm_nt<<<ggrid, gthreads>>>(x, Wk, bk, nullptr, 1);
    gemm_nt<<<ggrid, gthreads>>>(x, Wv, bv, nullptr, 2);

    attn_kernel<<<dim3((SEQ + QT - 1) / QT, BATCH * NHEAD), 128>>>();

    gemm_nt<<<ggrid, gthreads>>>(nullptr, Wo, bo, out, 3);
}

// round 6
// speedup vs baseline: 1.7128x; 1.7128x over previous
#include <cuda_runtime.h>
#include <cuda_bf16.h>
#include <float.h>
#include <math.h>
#include <cstdint>

// Problem constants
#define BATCH  32
#define SEQ    577
#define DMODEL 768
#define NHEAD  12
#define HDIM   64
#define MROWS  (BATCH * SEQ)                  // 18464
#define ELEMS  (MROWS * DMODEL)               // 14,180,352
#define WSZ    (DMODEL * DMODEL)              // 589,824

// fp32 scratch
__device__ float g_Q[ELEMS];    // [B, H, N, 64]
__device__ float g_K[ELEMS];
__device__ float g_V[ELEMS];
__device__ float g_ctx[ELEMS];  // [B*N, 768]

// bf16 hi/lo split scratch
__device__ __nv_bfloat16 g_xhi[ELEMS];
__device__ __nv_bfloat16 g_xlo[ELEMS];
__device__ __nv_bfloat16 g_chi[ELEMS];
__device__ __nv_bfloat16 g_clo[ELEMS];
__device__ __nv_bfloat16 g_whi[4 * WSZ];   // Wq, Wk, Wv, Wo
__device__ __nv_bfloat16 g_wlo[4 * WSZ];

// ---------------------------------------------------------------------------
// PTX helpers (plain sm_103-safe: mma.sync / ldmatrix / cp.async only)
// ---------------------------------------------------------------------------
__device__ __forceinline__ uint32_t smem_u32(const void* p) {
    uint32_t a;
    asm("{ .reg .u64 t; cvta.to.shared.u64 t, %1; cvt.u32.u64 %0, t; }" : "=r"(a) : "l"(p));
    return a;
}
__device__ __forceinline__ void cp_async16(uint32_t dst, const void* src, bool valid) {
    int sz = valid ? 16 : 0;
    asm volatile("cp.async.cg.shared.global [%0], [%1], 16, %2;"
                 :: "r"(dst), "l"(src), "r"(sz));
}
#define CP_COMMIT() asm volatile("cp.async.commit_group;" ::: "memory")
#define CP_WAIT(N)  asm volatile("cp.async.wait_group %0;" :: "n"(N) : "memory")

__device__ __forceinline__ void ldsm_x4(uint32_t* r, uint32_t addr) {
    asm volatile("ldmatrix.sync.aligned.m8n8.x4.shared.b16 {%0,%1,%2,%3}, [%4];"
                 : "=r"(r[0]), "=r"(r[1]), "=r"(r[2]), "=r"(r[3]) : "r"(addr));
}
__device__ __forceinline__ void ldsm_x2(uint32_t* r, uint32_t addr) {
    asm volatile("ldmatrix.sync.aligned.m8n8.x2.shared.b16 {%0,%1}, [%2];"
                 : "=r"(r[0]), "=r"(r[1]) : "r"(addr));
}
__device__ __forceinline__ void mma16816(float* c, const uint32_t* a, const uint32_t* b) {
    asm volatile(
        "mma.sync.aligned.m16n8k16.row.col.f32.bf16.bf16.f32 "
        "{%0,%1,%2,%3}, {%4,%5,%6,%7}, {%8,%9}, {%0,%1,%2,%3};"
        : "+f"(c[0]), "+f"(c[1]), "+f"(c[2]), "+f"(c[3])
        : "r"(a[0]), "r"(a[1]), "r"(a[2]), "r"(a[3]), "r"(b[0]), "r"(b[1]));
}

// ---------------------------------------------------------------------------
// hi/lo bf16 split converter.  sel: 0-3 = weights Wq/Wk/Wv/Wo (src arg);
// 4 = x (src arg); 5 = ctx (reads g_ctx).  n4 = element count / 4.
// ---------------------------------------------------------------------------
__global__ void split_bf16(const float* __restrict__ src, int sel, int n4)
{
    __nv_bfloat16 *hi, *lo;
    const float* s = src;
    if (sel < 4)      { hi = g_whi + (size_t)sel * WSZ; lo = g_wlo + (size_t)sel * WSZ; }
    else if (sel == 4){ hi = g_xhi; lo = g_xlo; }
    else              { hi = g_chi; lo = g_clo; s = g_ctx; }

    int i = blockIdx.x * blockDim.x + threadIdx.x;
    if (i >= n4) return;
    float4 v = ((const float4*)s)[i];
    __nv_bfloat16 h0 = __float2bfloat16(v.x);
    __nv_bfloat16 h1 = __float2bfloat16(v.y);
    __nv_bfloat16 h2 = __float2bfloat16(v.z);
    __nv_bfloat16 h3 = __float2bfloat16(v.w);
    __nv_bfloat16 l0 = __float2bfloat16(v.x - __bfloat162float(h0));
    __nv_bfloat16 l1 = __float2bfloat16(v.y - __bfloat162float(h1));
    __nv_bfloat16 l2 = __float2bfloat16(v.z - __bfloat162float(h2));
    __nv_bfloat16 l3 = __float2bfloat16(v.w - __bfloat162float(h3));
    ((__nv_bfloat162*)hi)[2 * i]     = __halves2bfloat162(h0, h1);
    ((__nv_bfloat162*)hi)[2 * i + 1] = __halves2bfloat162(h2, h3);
    ((__nv_bfloat162*)lo)[2 * i]     = __halves2bfloat162(l0, l1);
    ((__nv_bfloat162*)lo)[2 * i + 1] = __halves2bfloat162(l2, l3);
}

// ---------------------------------------------------------------------------
// bf16-split NT GEMM on warp-level HMMA (mma.sync m16n8k16):
//   out[m,n] = sum_k (Ahi+Alo)[m,k]*(Whi+Wlo)[n,k] + bias[n]   (3 terms)
//   mode 0/1/2: A = x split, scatter into g_Q/g_K/g_V as [B,H,N,64]
//   mode 3:     A = ctx split, row-major store to outp
// 128x128 CTA tile, 256 threads (8 warps, 2x4), K blocked by 32,
// cp.async double-buffered smem, 80B-padded rows (ldmatrix conflict-free).
// ---------------------------------------------------------------------------
#define BKG   32
#define NKB   (DMODEL / BKG)          // 24
#define ROWB  80                      // bytes per smem row (32 bf16 + 8 pad)
#define MATB  (128 * ROWB)            // 10240 bytes per matrix tile
#define BUFB  (4 * MATB)              // 40960 bytes per k-block buffer
#define GEMM_SMEM (2 * BUFB)          // 81920

extern __shared__ char dynsmem[];

__global__ __launch_bounds__(256)
void gemm_tc(const float* __restrict__ bias, float* __restrict__ outp, int mode)
{
    const __nv_bfloat16* Ahi = (mode < 3) ? g_xhi : g_chi;
    const __nv_bfloat16* Alo = (mode < 3) ? g_xlo : g_clo;
    const __nv_bfloat16* Bhi = g_whi + (size_t)mode * WSZ;
    const __nv_bfloat16* Blo = g_wlo + (size_t)mode * WSZ;

    const uint32_t sb = smem_u32(dynsmem);
    const int tid  = threadIdx.x;
    const int wid  = tid >> 5;
    const int lane = tid & 31;
    const int wm   = wid & 1;          // 2 m-slabs of 64
    const int wn   = wid >> 1;         // 4 n-slabs of 32
    const int block_m = blockIdx.y * 128;
    const int block_n = blockIdx.x * 128;

    float c[4][4][4];
#pragma unroll
    for (int mi = 0; mi < 4; mi++)
#pragma unroll
        for (int ni = 0; ni < 4; ni++)
#pragma unroll
            for (int r = 0; r < 4; r++) c[mi][ni][r] = 0.f;

    // Issue one k-block's loads into buffer `buf` (4 matrices x 128 rows x 64B)
    auto issue_load = [&](int kb, int buf) {
        const int k0 = kb * BKG;
#pragma unroll
        for (int it = 0; it < 8; it++) {
            int idx = tid + it * 256;          // 0..2047
            int mat = idx >> 9;                // 0..3
            int rem = idx & 511;
            int row = rem >> 2;                // 0..127
            int cc  = rem & 3;                 // 16B chunk
            const __nv_bfloat16* sp = (mat == 0) ? Ahi : (mat == 1) ? Alo
                                    : (mat == 2) ? Bhi : Blo;
            const int rb = (mat < 2) ? block_m : block_n;
            const bool guard = (mat < 2);
            int gr = rb + row;
            bool valid = !guard || (gr < MROWS);
            if (!valid) gr = 0;
            const void* src = sp + (size_t)gr * DMODEL + k0 + cc * 8;
            uint32_t dst = sb + buf * BUFB + mat * MATB + row * ROWB + cc * 16;
            cp_async16(dst, src, valid);
        }
        CP_COMMIT();
    };

    issue_load(0, 0);

    for (int kb = 0; kb < NKB; kb++) {
        const int buf = kb & 1;
        if (kb + 1 < NKB) issue_load(kb + 1, buf ^ 1);
        if (kb + 1 < NKB) { CP_WAIT(1); } else { CP_WAIT(0); }
        __syncthreads();

        const uint32_t bufb = sb + buf * BUFB;
#pragma unroll
        for (int kt = 0; kt < 2; kt++) {
            uint32_t afr[4][2][4];
            uint32_t bfr[4][2][2];
#pragma unroll
            for (int mi = 0; mi < 4; mi++) {
                int row  = wm * 64 + mi * 16 + (lane & 15);
                int kcol = kt * 16 + (lane >> 4) * 8;
                uint32_t a = bufb + row * ROWB + kcol * 2;
                ldsm_x4(afr[mi][0], a);
                ldsm_x4(afr[mi][1], a + MATB);
            }
#pragma unroll
            for (int ni = 0; ni < 4; ni++) {
                int nrow = wn * 32 + ni * 8 + (lane & 7);
                int kcol = kt * 16 + ((lane >> 3) & 1) * 8;
                uint32_t a = bufb + 2 * MATB + nrow * ROWB + kcol * 2;
                ldsm_x2(bfr[ni][0], a);
                ldsm_x2(bfr[ni][1], a + MATB);
            }
#pragma unroll
            for (int mi = 0; mi < 4; mi++)
#pragma unroll
                for (int ni = 0; ni < 4; ni++) {
                    mma16816(c[mi][ni], afr[mi][0], bfr[ni][0]);  // hi*hi
                    mma16816(c[mi][ni], afr[mi][0], bfr[ni][1]);  // hi*lo
                    mma16816(c[mi][ni], afr[mi][1], bfr[ni][0]);  // lo*hi
                }
        }
        __syncthreads();
    }

    // Epilogue: frag (mi,ni): rows gm0 = .. + lane/4 (+8), cols gn = .. + 2*(lane%4)
    float* scatter = (mode == 0) ? g_Q : (mode == 1) ? g_K : g_V;
#pragma unroll
    for (int mi = 0; mi < 4; mi++) {
#pragma unroll
        for (int half = 0; half < 2; half++) {
            int gm = block_m + wm * 64 + mi * 16 + (lane >> 2) + half * 8;
            if (gm >= MROWS) continue;
            int b_idx = gm / SEQ;
            int n_idx = gm - b_idx * SEQ;
#pragma unroll
            for (int ni = 0; ni < 4; ni++) {
                int gn = block_n + wn * 32 + ni * 8 + 2 * (lane & 3);
                float v0 = c[mi][ni][half * 2 + 0] + bias[gn];
                float v1 = c[mi][ni][half * 2 + 1] + bias[gn + 1];
                float* dst;
                if (mode <= 2) {
                    int h = gn >> 6, hd = gn & 63;
                    dst = scatter + (((size_t)b_idx * NHEAD + h) * SEQ + n_idx) * HDIM + hd;
                } else {
                    dst = outp + (size_t)gm * DMODEL + gn;
                }
                *(float2*)dst = make_float2(v0, v1);
            }
        }
    }
}

// ---------------------------------------------------------------------------
// Flash attention: anti-causal mask (k >= q), scale 1/sqrt(768).
// Thread PAIR per query: each thread owns 32 of 64 head dims; dot completed
// with one shfl_xor. 256 threads, 2 CTAs/SM (regs capped at 128).
// ---------------------------------------------------------------------------
#define QT 128
#define KT 32

__global__ __launch_bounds__(256, 2)
void attn_kernel()
{
    __shared__ float Ks[KT][HDIM];
    __shared__ float Vs[KT][HDIM];

    const int bh   = blockIdx.y;
    const int q0   = blockIdx.x * QT;
    const int tid  = threadIdx.x;
    const int lid  = tid & 31;
    const int q    = q0 + (tid >> 1);
    const int doff = (tid & 1) * 32;
    const bool active = (q < SEQ);
    const unsigned pmask = 3u << (lid & 30);

    const float* Kbase = g_K + (size_t)bh * SEQ * HDIM;
    const float* Vbase = g_V + (size_t)bh * SEQ * HDIM;

    float qv[32];
    if (active) {
        const float4* qp = (const float4*)(g_Q + (size_t)bh * SEQ * HDIM + (size_t)q * HDIM + doff);
#pragma unroll
        for (int i = 0; i < 8; i++) ((float4*)qv)[i] = qp[i];
    }

    float m = -FLT_MAX, l = 0.f;
    float acc[32];
#pragma unroll
    for (int d = 0; d < 32; d++) acc[d] = 0.f;

    const float scale = 0.03608439182435161f;   // 1/sqrt(768)

    for (int kc = q0; kc < SEQ; kc += KT) {
#pragma unroll
        for (int i = 0; i < 2; i++) {
            int gidx = tid + i * 256;
            int row  = gidx >> 4;
            int c4   = (gidx & 15) << 2;
            int gk   = kc + row;
            float4 kv = make_float4(0.f, 0.f, 0.f, 0.f);
            float4 vv = make_float4(0.f, 0.f, 0.f, 0.f);
            if (gk < SEQ) {
                kv = *(const float4*)(Kbase + (size_t)gk * HDIM + c4);
                vv = *(const float4*)(Vbase + (size_t)gk * HDIM + c4);
            }
            *(float4*)&Ks[row][c4] = kv;
            *(float4*)&Vs[row][c4] = vv;
        }
        __syncthreads();

        if (active && (kc + KT > q)) {
            float s[KT];
            float tmax = -FLT_MAX;
#pragma unroll
            for (int j = 0; j < KT; j++) {
                int k = kc + j;
                float partial = 0.f;
#pragma unroll
                for (int d = 0; d < 32; d++) partial += qv[d] * Ks[j][doff + d];
                float dot = partial + __shfl_xor_sync(pmask, partial, 1);
                s[j] = (k < SEQ && k >= q) ? dot * scale : -FLT_MAX;
                tmax = fmaxf(tmax, s[j]);
            }
            float mnew = fmaxf(m, tmax);
            float corr = __expf(m - mnew);
            l *= corr;
#pragma unroll
            for (int d = 0; d < 32; d++) acc[d] *= corr;
#pragma unroll
            for (int j = 0; j < KT; j++) {
                float p = __expf(s[j] - mnew);
                l += p;
#pragma unroll
                for (int d = 0; d < 32; d++) acc[d] += p * Vs[j][doff + d];
            }
            m = mnew;
        }
        __syncthreads();
    }

    if (active) {
        float inv = 1.f / l;
        int b = bh / NHEAD, h = bh - b * NHEAD;
        float* op = g_ctx + ((size_t)(b * SEQ + q)) * DMODEL + h * HDIM + doff;
#pragma unroll
        for (int i = 0; i < 8; i++) {
            float4 o;
            o.x = acc[i * 4 + 0] * inv;
            o.y = acc[i * 4 + 1] * inv;
            o.z = acc[i * 4 + 2] * inv;
            o.w = acc[i * 4 + 3] * inv;
            ((float4*)op)[i] = o;
        }
    }
}

// ---------------------------------------------------------------------------
extern "C" void kernel_launch(void* const* d_in, const int* in_sizes, int n_in,
                              void* d_out, int out_size)
{
    (void)in_sizes; (void)n_in; (void)out_size;
    const float* x  = (const float*)d_in[0];
    const float* Wq = (const float*)d_in[1];
    const float* bq = (const float*)d_in[2];
    const float* Wk = (const float*)d_in[3];
    const float* bk = (const float*)d_in[4];
    const float* Wv = (const float*)d_in[5];
    const float* bv = (const float*)d_in[6];
    const float* Wo = (const float*)d_in[7];
    const float* bo = (const float*)d_in[8];
    float* out = (float*)d_out;

    cudaFuncSetAttribute(gemm_tc, cudaFuncAttributeMaxDynamicSharedMemorySize, GEMM_SMEM);

    // hi/lo bf16 splits
    {
        int n4 = ELEMS / 4;
        split_bf16<<<(n4 + 255) / 256, 256>>>(x, 4, n4);
        int w4 = WSZ / 4;
        split_bf16<<<(w4 + 255) / 256, 256>>>(Wq, 0, w4);
        split_bf16<<<(w4 + 255) / 256, 256>>>(Wk, 1, w4);
        split_bf16<<<(w4 + 255) / 256, 256>>>(Wv, 2, w4);
        split_bf16<<<(w4 + 255) / 256, 256>>>(Wo, 3, w4);
    }

    dim3 ggrid(DMODEL / 128, (MROWS + 127) / 128);   // (6, 145)

    gemm_tc<<<ggrid, 256, GEMM_SMEM>>>(bq, nullptr, 0);
    gemm_tc<<<ggrid, 256, GEMM_SMEM>>>(bk, nullptr, 1);
    gemm_tc<<<ggrid, 256, GEMM_SMEM>>>(bv, nullptr, 2);

    attn_kernel<<<dim3((SEQ + QT - 1) / QT, BATCH * NHEAD), 256>>>();

    {
        int n4 = ELEMS / 4;
        split_bf16<<<(n4 + 255) / 256, 256>>>(nullptr, 5, n4);
    }
    gemm_tc<<<ggrid, 256, GEMM_SMEM>>>(bo, out, 3);
}

// round 8
// speedup vs baseline: 3.3967x; 1.9831x over previous
#include <cuda_runtime.h>
#include <cuda_bf16.h>
#include <float.h>
#include <math.h>
#include <cstdint>

// Problem constants
#define BATCH  32
#define SEQ    577
#define DMODEL 768
#define NHEAD  12
#define HDIM   64
#define MROWS  (BATCH * SEQ)                  // 18464
#define ELEMS  (MROWS * DMODEL)               // 14,180,352
#define WSZ    (DMODEL * DMODEL)              // 589,824

// bf16 hi/lo scratch
__device__ __nv_bfloat16 g_xhi[ELEMS];
__device__ __nv_bfloat16 g_xlo[ELEMS];
__device__ __nv_bfloat16 g_chi[ELEMS];     // ctx (attention output)
__device__ __nv_bfloat16 g_clo[ELEMS];
__device__ __nv_bfloat16 g_whi[4 * WSZ];   // Wq, Wk, Wv, Wo
__device__ __nv_bfloat16 g_wlo[4 * WSZ];
__device__ __nv_bfloat16 g_Qhi[ELEMS];     // [B,H,N,64]
__device__ __nv_bfloat16 g_Qlo[ELEMS];
__device__ __nv_bfloat16 g_Khi[ELEMS];
__device__ __nv_bfloat16 g_Klo[ELEMS];
__device__ __nv_bfloat16 g_Vhi[ELEMS];
__device__ __nv_bfloat16 g_Vlo[ELEMS];

// ---------------------------------------------------------------------------
// PTX helpers (plain sm_103-safe)
// ---------------------------------------------------------------------------
__device__ __forceinline__ uint32_t smem_u32(const void* p) {
    uint32_t a;
    asm("{ .reg .u64 t; cvta.to.shared.u64 t, %1; cvt.u32.u64 %0, t; }" : "=r"(a) : "l"(p));
    return a;
}
__device__ __forceinline__ void cp_async16(uint32_t dst, const void* src, bool valid) {
    int sz = valid ? 16 : 0;
    asm volatile("cp.async.cg.shared.global [%0], [%1], 16, %2;"
                 :: "r"(dst), "l"(src), "r"(sz));
}
#define CP_COMMIT() asm volatile("cp.async.commit_group;" ::: "memory")
#define CP_WAIT(N)  asm volatile("cp.async.wait_group %0;" :: "n"(N) : "memory")

__device__ __forceinline__ void ldsm_x4(uint32_t* r, uint32_t addr) {
    asm volatile("ldmatrix.sync.aligned.m8n8.x4.shared.b16 {%0,%1,%2,%3}, [%4];"
                 : "=r"(r[0]), "=r"(r[1]), "=r"(r[2]), "=r"(r[3]) : "r"(addr));
}
__device__ __forceinline__ void ldsm_x4t(uint32_t* r, uint32_t addr) {
    asm volatile("ldmatrix.sync.aligned.m8n8.x4.trans.shared.b16 {%0,%1,%2,%3}, [%4];"
                 : "=r"(r[0]), "=r"(r[1]), "=r"(r[2]), "=r"(r[3]) : "r"(addr));
}
__device__ __forceinline__ void mma16816(float* c, const uint32_t* a, const uint32_t* b) {
    asm volatile(
        "mma.sync.aligned.m16n8k16.row.col.f32.bf16.bf16.f32 "
        "{%0,%1,%2,%3}, {%4,%5,%6,%7}, {%8,%9}, {%0,%1,%2,%3};"
        : "+f"(c[0]), "+f"(c[1]), "+f"(c[2]), "+f"(c[3])
        : "r"(a[0]), "r"(a[1]), "r"(a[2]), "r"(a[3]), "r"(b[0]), "r"(b[1]));
}
__device__ __forceinline__ uint32_t bf2_bits(__nv_bfloat16 a, __nv_bfloat16 b) {
    __nv_bfloat162 v = __halves2bfloat162(a, b);
    return *(uint32_t*)&v;
}

// ---------------------------------------------------------------------------
// hi/lo bf16 split converter.  sel 0-3 = weights Wq/Wk/Wv/Wo; 4 = x.
// ---------------------------------------------------------------------------
__global__ void split_bf16(const float* __restrict__ src, int sel, int n4)
{
    __nv_bfloat16 *hi, *lo;
    if (sel < 4) { hi = g_whi + (size_t)sel * WSZ; lo = g_wlo + (size_t)sel * WSZ; }
    else         { hi = g_xhi; lo = g_xlo; }

    int i = blockIdx.x * blockDim.x + threadIdx.x;
    if (i >= n4) return;
    float4 v = ((const float4*)src)[i];
    __nv_bfloat16 h0 = __float2bfloat16(v.x);
    __nv_bfloat16 h1 = __float2bfloat16(v.y);
    __nv_bfloat16 h2 = __float2bfloat16(v.z);
    __nv_bfloat16 h3 = __float2bfloat16(v.w);
    ((uint32_t*)hi)[2 * i]     = bf2_bits(h0, h1);
    ((uint32_t*)hi)[2 * i + 1] = bf2_bits(h2, h3);
    ((uint32_t*)lo)[2 * i]     = bf2_bits(__float2bfloat16(v.x - __bfloat162float(h0)),
                                          __float2bfloat16(v.y - __bfloat162float(h1)));
    ((uint32_t*)lo)[2 * i + 1] = bf2_bits(__float2bfloat16(v.z - __bfloat162float(h2)),
                                          __float2bfloat16(v.w - __bfloat162float(h3)));
}

// ---------------------------------------------------------------------------
// bf16-split NT GEMM (mma.sync m16n8k16, 3 terms).
// QKV=1: fused QKV. grid.x = 18; mat = x/6. A = x split.
//        Epilogue: bias add, then hi/lo bf16 scatter into g_{Q,K,V}{hi,lo}
//        as [B,H,N,64].
// QKV=0: output projection. A = ctx split, W = Wo, fp32 store to outp.
// ---------------------------------------------------------------------------
#define BKG   32
#define NKB   (DMODEL / BKG)          // 24
#define ROWB  80
#define MATB  (128 * ROWB)            // 10240
#define BUFB  (4 * MATB)              // 40960
#define GEMM_SMEM (2 * BUFB)          // 81920

extern __shared__ char dynsmem[];

template<int QKV>
__global__ __launch_bounds__(256)
void gemm_tc(const float* __restrict__ b0, const float* __restrict__ b1,
             const float* __restrict__ b2, float* __restrict__ outp)
{
    const int mat = QKV ? (blockIdx.x / 6) : 3;
    const int bx  = QKV ? (blockIdx.x % 6) : blockIdx.x;
    const __nv_bfloat16* Ahi = QKV ? g_xhi : g_chi;
    const __nv_bfloat16* Alo = QKV ? g_xlo : g_clo;
    const __nv_bfloat16* Bhi = g_whi + (size_t)mat * WSZ;
    const __nv_bfloat16* Blo = g_wlo + (size_t)mat * WSZ;
    const float* bias = QKV ? (mat == 0 ? b0 : mat == 1 ? b1 : b2) : b0;

    const uint32_t sb = smem_u32(dynsmem);
    const int tid  = threadIdx.x;
    const int wid  = tid >> 5;
    const int lane = tid & 31;
    const int wm   = wid & 1;
    const int wn   = wid >> 1;
    const int block_m = blockIdx.y * 128;
    const int block_n = bx * 128;

    float c[4][4][4];
#pragma unroll
    for (int mi = 0; mi < 4; mi++)
#pragma unroll
        for (int ni = 0; ni < 4; ni++)
#pragma unroll
            for (int r = 0; r < 4; r++) c[mi][ni][r] = 0.f;

    auto issue_load = [&](int kb, int buf) {
        const int k0 = kb * BKG;
#pragma unroll
        for (int it = 0; it < 8; it++) {
            int idx = tid + it * 256;
            int m   = idx >> 9;
            int rem = idx & 511;
            int row = rem >> 2;
            int cc  = rem & 3;
            const __nv_bfloat16* sp = (m == 0) ? Ahi : (m == 1) ? Alo
                                    : (m == 2) ? Bhi : Blo;
            const int rb = (m < 2) ? block_m : block_n;
            const bool guard = (m < 2);
            int gr = rb + row;
            bool valid = !guard || (gr < MROWS);
            if (!valid) gr = 0;
            const void* src = sp + (size_t)gr * DMODEL + k0 + cc * 8;
            uint32_t dst = sb + buf * BUFB + m * MATB + row * ROWB + cc * 16;
            cp_async16(dst, src, valid);
        }
        CP_COMMIT();
    };

    issue_load(0, 0);

    for (int kb = 0; kb < NKB; kb++) {
        const int buf = kb & 1;
        if (kb + 1 < NKB) issue_load(kb + 1, buf ^ 1);
        if (kb + 1 < NKB) { CP_WAIT(1); } else { CP_WAIT(0); }
        __syncthreads();

        const uint32_t bufb = sb + buf * BUFB;
#pragma unroll
        for (int kt = 0; kt < 2; kt++) {
            uint32_t afr[4][2][4];
            uint32_t bfr[4][2][2];
#pragma unroll
            for (int mi = 0; mi < 4; mi++) {
                int row  = wm * 64 + mi * 16 + (lane & 15);
                int kcol = kt * 16 + (lane >> 4) * 8;
                uint32_t a = bufb + row * ROWB + kcol * 2;
                ldsm_x4(afr[mi][0], a);
                ldsm_x4(afr[mi][1], a + MATB);
            }
#pragma unroll
            for (int ni = 0; ni < 4; ni++) {
                int nrow = wn * 32 + ni * 8 + (lane & 7);
                int kcol = kt * 16 + ((lane >> 3) & 1) * 8;
                uint32_t a = bufb + 2 * MATB + nrow * ROWB + kcol * 2;
                asm volatile("ldmatrix.sync.aligned.m8n8.x2.shared.b16 {%0,%1}, [%2];"
                             : "=r"(bfr[ni][0][0]), "=r"(bfr[ni][0][1]) : "r"(a));
                asm volatile("ldmatrix.sync.aligned.m8n8.x2.shared.b16 {%0,%1}, [%2];"
                             : "=r"(bfr[ni][1][0]), "=r"(bfr[ni][1][1]) : "r"(a + MATB));
            }
#pragma unroll
            for (int mi = 0; mi < 4; mi++)
#pragma unroll
                for (int ni = 0; ni < 4; ni++) {
                    mma16816(c[mi][ni], afr[mi][0], bfr[ni][0]);
                    mma16816(c[mi][ni], afr[mi][0], bfr[ni][1]);
                    mma16816(c[mi][ni], afr[mi][1], bfr[ni][0]);
                }
        }
        __syncthreads();
    }

    __nv_bfloat16* hid = (mat == 0) ? g_Qhi : (mat == 1) ? g_Khi : g_Vhi;
    __nv_bfloat16* lod = (mat == 0) ? g_Qlo : (mat == 1) ? g_Klo : g_Vlo;
#pragma unroll
    for (int mi = 0; mi < 4; mi++) {
#pragma unroll
        for (int half = 0; half < 2; half++) {
            int gm = block_m + wm * 64 + mi * 16 + (lane >> 2) + half * 8;
            if (gm >= MROWS) continue;
            int b_idx = gm / SEQ;
            int n_idx = gm - b_idx * SEQ;
#pragma unroll
            for (int ni = 0; ni < 4; ni++) {
                int gn = block_n + wn * 32 + ni * 8 + 2 * (lane & 3);
                float v0 = c[mi][ni][half * 2 + 0] + bias[gn];
                float v1 = c[mi][ni][half * 2 + 1] + bias[gn + 1];
                if (QKV) {
                    int h = gn >> 6, hd = gn & 63;
                    size_t off = (((size_t)b_idx * NHEAD + h) * SEQ + n_idx) * HDIM + hd;
                    __nv_bfloat16 h0 = __float2bfloat16(v0);
                    __nv_bfloat16 h1 = __float2bfloat16(v1);
                    *(uint32_t*)(hid + off) = bf2_bits(h0, h1);
                    *(uint32_t*)(lod + off) = bf2_bits(
                        __float2bfloat16(v0 - __bfloat162float(h0)),
                        __float2bfloat16(v1 - __bfloat162float(h1)));
                } else {
                    *(float2*)(outp + (size_t)gm * DMODEL + gn) = make_float2(v0, v1);
                }
            }
        }
    }
}

// ---------------------------------------------------------------------------
// MMA flash attention: anti-causal (k >= q), scale 1/sqrt(768).
// CTA = (b,h, 64-query tile); 4 warps x 16 rows. 64-key tiles, cp.async
// double-buffered. S and PV via mma.sync with 3-term bf16 hi/lo splits.
// Output written as ctx hi/lo directly.
// ---------------------------------------------------------------------------
#define KROWB  144                    // 64 bf16 + 16B pad
#define ATILEB (64 * KROWB)           // 9216
#define ABUF0  (2 * ATILEB)           // after Qhi, Qlo
#define ABUFSZ (4 * ATILEB)           // Khi, Klo, Vhi, Vlo
#define ATT_SMEM (2 * ATILEB + 2 * ABUFSZ)   // 92160

__global__ __launch_bounds__(128, 2)
void attn_mma()
{
    const int bh  = blockIdx.y;
    const int q0  = blockIdx.x * 64;
    const int tid = threadIdx.x;
    const int wid = tid >> 5;
    const int lane = tid & 31;
    const uint32_t sb = smem_u32(dynsmem);
    const size_t base = (size_t)bh * SEQ * HDIM;
    const float SCALE = 0.03608439182435161f;   // 1/sqrt(768)

    // Q tiles (hi/lo), group G0
#pragma unroll
    for (int it = 0; it < 8; it++) {
        int idx = tid + it * 128;
        int m   = idx >> 9;
        int row = (idx >> 3) & 63;
        int cc  = idx & 7;
        int gq  = q0 + row;
        bool valid = gq < SEQ;
        const __nv_bfloat16* sp = m ? g_Qlo : g_Qhi;
        cp_async16(sb + m * ATILEB + row * KROWB + cc * 16,
                   sp + base + (size_t)(valid ? gq : 0) * HDIM + cc * 8, valid);
    }
    CP_COMMIT();

    auto issue_kv = [&](int kc, int stage) {
#pragma unroll
        for (int it = 0; it < 16; it++) {
            int idx = tid + it * 128;
            int m   = idx >> 9;
            int row = (idx >> 3) & 63;
            int cc  = idx & 7;
            int gk  = kc + row;
            bool valid = gk < SEQ;
            const __nv_bfloat16* sp = (m == 0) ? g_Khi : (m == 1) ? g_Klo
                                    : (m == 2) ? g_Vhi : g_Vlo;
            cp_async16(sb + ABUF0 + stage * ABUFSZ + m * ATILEB + row * KROWB + cc * 16,
                       sp + base + (size_t)(valid ? gk : 0) * HDIM + cc * 8, valid);
        }
        CP_COMMIT();
    };
    issue_kv(q0, 0);            // group G1

    // Q fragments
    CP_WAIT(1);
    __syncthreads();
    uint32_t qh[4][4], ql[4][4];
#pragma unroll
    for (int ks = 0; ks < 4; ks++) {
        uint32_t a = sb + (wid * 16 + (lane & 15)) * KROWB + ks * 32 + (lane >> 4) * 16;
        ldsm_x4(qh[ks], a);
        ldsm_x4(ql[ks], a + ATILEB);
    }

    float o[8][4];
#pragma unroll
    for (int vi = 0; vi < 8; vi++)
#pragma unroll
        for (int r = 0; r < 4; r++) o[vi][r] = 0.f;
    float m0 = -FLT_MAX, m1 = -FLT_MAX, l0 = 0.f, l1 = 0.f;

    const int qrow0 = q0 + wid * 16 + (lane >> 2);
    const int nkt = (SEQ - q0 + 63) / 64;

    for (int kt = 0; kt < nkt; kt++) {
        const int kc = q0 + kt * 64;
        const int stage = kt & 1;
        CP_WAIT(0);
        __syncthreads();
        if (kt + 1 < nkt) issue_kv(kc + 64, stage ^ 1);
        const uint32_t kb = sb + ABUF0 + stage * ABUFSZ;

        // ---- S = Q K^T (raw dots, 3-term)
        float s[8][4];
#pragma unroll
        for (int ni = 0; ni < 8; ni++)
#pragma unroll
            for (int r = 0; r < 4; r++) s[ni][r] = 0.f;
#pragma unroll
        for (int ks = 0; ks < 4; ks++) {
#pragma unroll
            for (int nip = 0; nip < 4; nip++) {
                uint32_t bh4[4], bl4[4];
                uint32_t a = kb + (nip * 16 + (lane >> 4) * 8 + (lane & 7)) * KROWB
                           + ks * 32 + ((lane >> 3) & 1) * 16;
                ldsm_x4(bh4, a);
                ldsm_x4(bl4, a + ATILEB);
                mma16816(s[2 * nip],     qh[ks], bh4);
                mma16816(s[2 * nip],     qh[ks], bl4);
                mma16816(s[2 * nip],     ql[ks], bh4);
                mma16816(s[2 * nip + 1], qh[ks], bh4 + 2);
                mma16816(s[2 * nip + 1], qh[ks], bl4 + 2);
                mma16816(s[2 * nip + 1], ql[ks], bh4 + 2);
            }
        }

        // ---- mask (diagonal tile and/or SEQ boundary)
        if (kt == 0 || kc + 64 > SEQ) {
#pragma unroll
            for (int ni = 0; ni < 8; ni++)
#pragma unroll
                for (int r = 0; r < 4; r++) {
                    int key = kc + ni * 8 + 2 * (lane & 3) + (r & 1);
                    int qq  = qrow0 + (r >> 1) * 8;
                    if (key < qq || key >= SEQ) s[ni][r] = -FLT_MAX;
                }
        }

        // ---- online softmax
        float t0 = -FLT_MAX, t1 = -FLT_MAX;
#pragma unroll
        for (int ni = 0; ni < 8; ni++) {
            t0 = fmaxf(t0, fmaxf(s[ni][0], s[ni][1]));
            t1 = fmaxf(t1, fmaxf(s[ni][2], s[ni][3]));
        }
        t0 = fmaxf(t0, __shfl_xor_sync(0xffffffffu, t0, 1));
        t0 = fmaxf(t0, __shfl_xor_sync(0xffffffffu, t0, 2));
        t1 = fmaxf(t1, __shfl_xor_sync(0xffffffffu, t1, 1));
        t1 = fmaxf(t1, __shfl_xor_sync(0xffffffffu, t1, 2));
        float mn0 = fmaxf(m0, t0), mn1 = fmaxf(m1, t1);
        float c0 = __expf((m0 - mn0) * SCALE);
        float c1 = __expf((m1 - mn1) * SCALE);
        m0 = mn0; m1 = mn1;
        l0 *= c0;  l1 *= c1;
#pragma unroll
        for (int vi = 0; vi < 8; vi++) {
            o[vi][0] *= c0; o[vi][1] *= c0;
            o[vi][2] *= c1; o[vi][3] *= c1;
        }

        // ---- P = exp, pack hi/lo a-fragments
        uint32_t pa[4][4], pl[4][4];
#pragma unroll
        for (int ni = 0; ni < 8; ni++) {
            float p0 = __expf((s[ni][0] - m0) * SCALE);
            float p1 = __expf((s[ni][1] - m0) * SCALE);
            float p2 = __expf((s[ni][2] - m1) * SCALE);
            float p3 = __expf((s[ni][3] - m1) * SCALE);
            l0 += p0 + p1;  l1 += p2 + p3;
            __nv_bfloat16 h0 = __float2bfloat16(p0), h1 = __float2bfloat16(p1);
            __nv_bfloat16 h2 = __float2bfloat16(p2), h3 = __float2bfloat16(p3);
            int kj = ni >> 1;
            int rg = (ni & 1) * 2;
            pa[kj][rg]     = bf2_bits(h0, h1);
            pa[kj][rg + 1] = bf2_bits(h2, h3);
            pl[kj][rg]     = bf2_bits(__float2bfloat16(p0 - __bfloat162float(h0)),
                                      __float2bfloat16(p1 - __bfloat162float(h1)));
            pl[kj][rg + 1] = bf2_bits(__float2bfloat16(p2 - __bfloat162float(h2)),
                                      __float2bfloat16(p3 - __bfloat162float(h3)));
        }

        // ---- O += P V  (V frags via ldmatrix.trans, 3-term)
#pragma unroll
        for (int kj = 0; kj < 4; kj++) {
#pragma unroll
            for (int vip = 0; vip < 4; vip++) {
                uint32_t vh4[4], vl4[4];
                uint32_t a = kb + 2 * ATILEB
                           + (kj * 16 + ((lane >> 3) & 1) * 8 + (lane & 7)) * KROWB
                           + vip * 32 + (lane >> 4) * 16;
                ldsm_x4t(vh4, a);
                ldsm_x4t(vl4, a + ATILEB);
                mma16816(o[2 * vip],     pa[kj], vh4);
                mma16816(o[2 * vip],     pa[kj], vl4);
                mma16816(o[2 * vip],     pl[kj], vh4);
                mma16816(o[2 * vip + 1], pa[kj], vh4 + 2);
                mma16816(o[2 * vip + 1], pa[kj], vl4 + 2);
                mma16816(o[2 * vip + 1], pl[kj], vh4 + 2);
            }
        }
    }

    // ---- epilogue
    l0 += __shfl_xor_sync(0xffffffffu, l0, 1);
    l0 += __shfl_xor_sync(0xffffffffu, l0, 2);
    l1 += __shfl_xor_sync(0xffffffffu, l1, 1);
    l1 += __shfl_xor_sync(0xffffffffu, l1, 2);
    float inv0 = 1.f / l0, inv1 = 1.f / l1;

    const int b = bh / NHEAD, h = bh - b * NHEAD;
#pragma unroll
    for (int half = 0; half < 2; half++) {
        int q = q0 + wid * 16 + (lane >> 2) + half * 8;
        if (q >= SEQ) continue;
        size_t rowb = ((size_t)(b * SEQ + q)) * DMODEL + h * HDIM;
        float inv = half ? inv1 : inv0;
#pragma unroll
        for (int vi = 0; vi < 8; vi++) {
            int d = vi * 8 + 2 * (lane & 3);
            float a  = o[vi][half * 2 + 0] * inv;
            float bb = o[vi][half * 2 + 1] * inv;
            __nv_bfloat16 ha = __float2bfloat16(a);
            __nv_bfloat16 hb = __float2bfloat16(bb);
            *(uint32_t*)(g_chi + rowb + d) = bf2_bits(ha, hb);
            *(uint32_t*)(g_clo + rowb + d) = bf2_bits(
                __float2bfloat16(a - __bfloat162float(ha)),
                __float2bfloat16(bb - __bfloat162float(hb)));
        }
    }
}

// ---------------------------------------------------------------------------
extern "C" void kernel_launch(void* const* d_in, const int* in_sizes, int n_in,
                              void* d_out, int out_size)
{
    (void)in_sizes; (void)n_in; (void)out_size;
    const float* x  = (const float*)d_in[0];
    const float* Wq = (const float*)d_in[1];
    const float* bq = (const float*)d_in[2];
    const float* Wk = (const float*)d_in[3];
    const float* bk = (const float*)d_in[4];
    const float* Wv = (const float*)d_in[5];
    const float* bv = (const float*)d_in[6];
    const float* Wo = (const float*)d_in[7];
    const float* bo = (const float*)d_in[8];
    float* out = (float*)d_out;

    cudaFuncSetAttribute(gemm_tc<1>, cudaFuncAttributeMaxDynamicSharedMemorySize, GEMM_SMEM);
    cudaFuncSetAttribute(gemm_tc<0>, cudaFuncAttributeMaxDynamicSharedMemorySize, GEMM_SMEM);
    cudaFuncSetAttribute(attn_mma,   cudaFuncAttributeMaxDynamicSharedMemorySize, ATT_SMEM);

    {
        int n4 = ELEMS / 4;
        split_bf16<<<(n4 + 255) / 256, 256>>>(x, 4, n4);
        int w4 = WSZ / 4;
        split_bf16<<<(w4 + 255) / 256, 256>>>(Wq, 0, w4);
        split_bf16<<<(w4 + 255) / 256, 256>>>(Wk, 1, w4);
        split_bf16<<<(w4 + 255) / 256, 256>>>(Wv, 2, w4);
        split_bf16<<<(w4 + 255) / 256, 256>>>(Wo, 3, w4);
    }

    // Fused QKV projection (18 n-tiles = 3 matrices x 6)
    gemm_tc<1><<<dim3(18, (MROWS + 127) / 128), 256, GEMM_SMEM>>>(bq, bk, bv, nullptr);

    // MMA flash attention
    attn_mma<<<dim3((SEQ + 63) / 64, BATCH * NHEAD), 128, ATT_SMEM>>>();

    // Output projection
    gemm_tc<0><<<dim3(6, (MROWS + 127) / 128), 256, GEMM_SMEM>>>(bo, nullptr, nullptr, out);
}

// round 9
// speedup vs baseline: 7.3547x; 2.1653x over previous
#include <cuda_runtime.h>
#include <cuda_fp16.h>
#include <float.h>
#include <math.h>
#include <cstdint>

// Problem constants
#define BATCH  32
#define SEQ    577
#define DMODEL 768
#define NHEAD  12
#define HDIM   64
#define MROWS  (BATCH * SEQ)                  // 18464
#define ELEMS  (MROWS * DMODEL)               // 14,180,352
#define WSZ    (DMODEL * DMODEL)              // 589,824

// fp16 scratch
__device__ __half g_xh[ELEMS];      // x
__device__ __half g_ch[ELEMS];      // ctx (attention output)
__device__ __half g_wh[4 * WSZ];    // Wq, Wk, Wv, Wo
__device__ __half g_Qh[ELEMS];      // [B,H,N,64]
__device__ __half g_Kh[ELEMS];
__device__ __half g_Vh[ELEMS];

// ---------------------------------------------------------------------------
// PTX helpers (plain sm_103-safe)
// ---------------------------------------------------------------------------
__device__ __forceinline__ uint32_t smem_u32(const void* p) {
    uint32_t a;
    asm("{ .reg .u64 t; cvta.to.shared.u64 t, %1; cvt.u32.u64 %0, t; }" : "=r"(a) : "l"(p));
    return a;
}
__device__ __forceinline__ void cp_async16(uint32_t dst, const void* src, bool valid) {
    int sz = valid ? 16 : 0;
    asm volatile("cp.async.cg.shared.global [%0], [%1], 16, %2;"
                 :: "r"(dst), "l"(src), "r"(sz));
}
#define CP_COMMIT() asm volatile("cp.async.commit_group;" ::: "memory")
#define CP_WAIT(N)  asm volatile("cp.async.wait_group %0;" :: "n"(N) : "memory")

__device__ __forceinline__ void ldsm_x4(uint32_t* r, uint32_t addr) {
    asm volatile("ldmatrix.sync.aligned.m8n8.x4.shared.b16 {%0,%1,%2,%3}, [%4];"
                 : "=r"(r[0]), "=r"(r[1]), "=r"(r[2]), "=r"(r[3]) : "r"(addr));
}
__device__ __forceinline__ void ldsm_x2(uint32_t* r, uint32_t addr) {
    asm volatile("ldmatrix.sync.aligned.m8n8.x2.shared.b16 {%0,%1}, [%2];"
                 : "=r"(r[0]), "=r"(r[1]) : "r"(addr));
}
__device__ __forceinline__ void ldsm_x4t(uint32_t* r, uint32_t addr) {
    asm volatile("ldmatrix.sync.aligned.m8n8.x4.trans.shared.b16 {%0,%1,%2,%3}, [%4];"
                 : "=r"(r[0]), "=r"(r[1]), "=r"(r[2]), "=r"(r[3]) : "r"(addr));
}
__device__ __forceinline__ void mma16816h(float* c, const uint32_t* a, const uint32_t* b) {
    asm volatile(
        "mma.sync.aligned.m16n8k16.row.col.f32.f16.f16.f32 "
        "{%0,%1,%2,%3}, {%4,%5,%6,%7}, {%8,%9}, {%0,%1,%2,%3};"
        : "+f"(c[0]), "+f"(c[1]), "+f"(c[2]), "+f"(c[3])
        : "r"(a[0]), "r"(a[1]), "r"(a[2]), "r"(a[3]), "r"(b[0]), "r"(b[1]));
}
__device__ __forceinline__ uint32_t h2_bits(float a, float b) {
    __half2 v = __floats2half2_rn(a, b);
    return *(uint32_t*)&v;
}

// ---------------------------------------------------------------------------
// fp32 -> fp16 converter.  sel 0-3 = weights Wq/Wk/Wv/Wo; 4 = x.
// ---------------------------------------------------------------------------
__global__ void to_fp16(const float* __restrict__ src, int sel, int n4)
{
    __half* dst = (sel < 4) ? (g_wh + (size_t)sel * WSZ) : g_xh;
    int i = blockIdx.x * blockDim.x + threadIdx.x;
    if (i >= n4) return;
    float4 v = ((const float4*)src)[i];
    ((uint32_t*)dst)[2 * i]     = h2_bits(v.x, v.y);
    ((uint32_t*)dst)[2 * i + 1] = h2_bits(v.z, v.w);
}

// ---------------------------------------------------------------------------
// fp16 NT GEMM (mma.sync m16n8k16, single pass, fp32 accum).
// QKV=1: fused QKV projection. grid.x = 18; mat = x/6; A = g_xh.
//        Epilogue: bias add, fp16 scatter into g_{Q,K,V}h as [B,H,N,64].
// QKV=0: output projection. A = g_ch, W = Wo, fp32 store to outp.
// 128x128 CTA tile, 8 warps (2m x 4n), K blocked by 32, 3-stage cp.async.
// ---------------------------------------------------------------------------
#define BKG   32
#define NKB   (DMODEL / BKG)          // 24
#define ROWB  80                      // 32 fp16 = 64B + 16B pad
#define MATB  (128 * ROWB)            // 10240
#define BUFB  (2 * MATB)              // 20480  (A, B)
#define GEMM_SMEM (3 * BUFB)          // 61440

extern __shared__ char dynsmem[];

template<int QKV>
__global__ __launch_bounds__(256)
void gemm_tc(const float* __restrict__ b0, const float* __restrict__ b1,
             const float* __restrict__ b2, float* __restrict__ outp)
{
    const int mat = QKV ? (blockIdx.x / 6) : 3;
    const int bx  = QKV ? (blockIdx.x % 6) : blockIdx.x;
    const __half* A = QKV ? g_xh : g_ch;
    const __half* B = g_wh + (size_t)mat * WSZ;
    const float* bias = QKV ? (mat == 0 ? b0 : mat == 1 ? b1 : b2) : b0;

    const uint32_t sb = smem_u32(dynsmem);
    const int tid  = threadIdx.x;
    const int wid  = tid >> 5;
    const int lane = tid & 31;
    const int wm   = wid & 1;
    const int wn   = wid >> 1;
    const int block_m = blockIdx.y * 128;
    const int block_n = bx * 128;

    float c[4][4][4];
#pragma unroll
    for (int mi = 0; mi < 4; mi++)
#pragma unroll
        for (int ni = 0; ni < 4; ni++)
#pragma unroll
            for (int r = 0; r < 4; r++) c[mi][ni][r] = 0.f;

    auto issue_load = [&](int kb, int buf) {
        const int k0 = kb * BKG;
#pragma unroll
        for (int it = 0; it < 4; it++) {
            int idx = tid + it * 256;          // 0..1023
            int m   = idx >> 9;                // 0..1
            int rem = idx & 511;
            int row = rem >> 2;                // 0..127
            int cc  = rem & 3;
            const __half* sp = m ? B : A;
            const int rb = m ? block_n : block_m;
            int gr = rb + row;
            bool valid = m || (gr < MROWS);
            if (!valid) gr = 0;
            cp_async16(sb + buf * BUFB + m * MATB + row * ROWB + cc * 16,
                       sp + (size_t)gr * DMODEL + k0 + cc * 8, valid);
        }
        CP_COMMIT();
    };

    issue_load(0, 0);
    issue_load(1, 1);

    for (int kb = 0; kb < NKB; kb++) {
        if (kb < NKB - 1) { CP_WAIT(1); } else { CP_WAIT(0); }
        __syncthreads();
        if (kb + 2 < NKB) issue_load(kb + 2, (kb + 2) % 3);

        const uint32_t bufb = sb + (kb % 3) * BUFB;
#pragma unroll
        for (int kt = 0; kt < 2; kt++) {
            uint32_t afr[4][4];
            uint32_t bfr[4][2];
#pragma unroll
            for (int mi = 0; mi < 4; mi++) {
                int row  = wm * 64 + mi * 16 + (lane & 15);
                int kcol = kt * 16 + (lane >> 4) * 8;
                ldsm_x4(afr[mi], bufb + row * ROWB + kcol * 2);
            }
#pragma unroll
            for (int ni = 0; ni < 4; ni++) {
                int nrow = wn * 32 + ni * 8 + (lane & 7);
                int kcol = kt * 16 + ((lane >> 3) & 1) * 8;
                ldsm_x2(bfr[ni], bufb + MATB + nrow * ROWB + kcol * 2);
            }
#pragma unroll
            for (int mi = 0; mi < 4; mi++)
#pragma unroll
                for (int ni = 0; ni < 4; ni++)
                    mma16816h(c[mi][ni], afr[mi], bfr[ni]);
        }
        __syncthreads();
    }

    __half* qkvd = (mat == 0) ? g_Qh : (mat == 1) ? g_Kh : g_Vh;
#pragma unroll
    for (int mi = 0; mi < 4; mi++) {
#pragma unroll
        for (int half = 0; half < 2; half++) {
            int gm = block_m + wm * 64 + mi * 16 + (lane >> 2) + half * 8;
            if (gm >= MROWS) continue;
            int b_idx = gm / SEQ;
            int n_idx = gm - b_idx * SEQ;
#pragma unroll
            for (int ni = 0; ni < 4; ni++) {
                int gn = block_n + wn * 32 + ni * 8 + 2 * (lane & 3);
                float v0 = c[mi][ni][half * 2 + 0] + bias[gn];
                float v1 = c[mi][ni][half * 2 + 1] + bias[gn + 1];
                if (QKV) {
                    int h = gn >> 6, hd = gn & 63;
                    size_t off = (((size_t)b_idx * NHEAD + h) * SEQ + n_idx) * HDIM + hd;
                    *(uint32_t*)(qkvd + off) = h2_bits(v0, v1);
                } else {
                    *(float2*)(outp + (size_t)gm * DMODEL + gn) = make_float2(v0, v1);
                }
            }
        }
    }
}

// ---------------------------------------------------------------------------
// MMA flash attention (fp16 single pass): anti-causal (k >= q), 1/sqrt(768).
// CTA = (b,h, 64-query tile); 4 warps x 16 rows; 64-key tiles, cp.async
// double-buffered. Output written as fp16 ctx directly.
// ---------------------------------------------------------------------------
#define KROWB  144                    // 64 fp16 = 128B + 16B pad
#define ATILEB (64 * KROWB)           // 9216
#define ABUF0  ATILEB                 // after Q tile
#define KVBUF  (2 * ATILEB)           // K, V
#define ATT_SMEM (ATILEB + 2 * KVBUF) // 46080

__global__ __launch_bounds__(128, 3)
void attn_mma()
{
    const int bh  = blockIdx.y;
    const int q0  = blockIdx.x * 64;
    const int tid = threadIdx.x;
    const int wid = tid >> 5;
    const int lane = tid & 31;
    const uint32_t sb = smem_u32(dynsmem);
    const size_t base = (size_t)bh * SEQ * HDIM;
    const float SCALE = 0.03608439182435161f;   // 1/sqrt(768)

    // Q tile
#pragma unroll
    for (int it = 0; it < 4; it++) {
        int idx = tid + it * 128;          // 0..511
        int row = idx >> 3;
        int cc  = idx & 7;
        int gq  = q0 + row;
        bool valid = gq < SEQ;
        cp_async16(sb + row * KROWB + cc * 16,
                   g_Qh + base + (size_t)(valid ? gq : 0) * HDIM + cc * 8, valid);
    }
    CP_COMMIT();

    auto issue_kv = [&](int kc, int stage) {
#pragma unroll
        for (int it = 0; it < 8; it++) {
            int idx = tid + it * 128;      // 0..1023
            int m   = idx >> 9;            // 0 = K, 1 = V
            int row = (idx >> 3) & 63;
            int cc  = idx & 7;
            int gk  = kc + row;
            bool valid = gk < SEQ;
            const __half* sp = m ? g_Vh : g_Kh;
            cp_async16(sb + ABUF0 + stage * KVBUF + m * ATILEB + row * KROWB + cc * 16,
                       sp + base + (size_t)(valid ? gk : 0) * HDIM + cc * 8, valid);
        }
        CP_COMMIT();
    };
    issue_kv(q0, 0);

    // Q fragments
    CP_WAIT(1);
    __syncthreads();
    uint32_t qh[4][4];
#pragma unroll
    for (int ks = 0; ks < 4; ks++)
        ldsm_x4(qh[ks], sb + (wid * 16 + (lane & 15)) * KROWB + ks * 32 + (lane >> 4) * 16);

    float o[8][4];
#pragma unroll
    for (int vi = 0; vi < 8; vi++)
#pragma unroll
        for (int r = 0; r < 4; r++) o[vi][r] = 0.f;
    float m0 = -FLT_MAX, m1 = -FLT_MAX, l0 = 0.f, l1 = 0.f;

    const int qrow0 = q0 + wid * 16 + (lane >> 2);
    const int nkt = (SEQ - q0 + 63) / 64;

    for (int kt = 0; kt < nkt; kt++) {
        const int kc = q0 + kt * 64;
        const int stage = kt & 1;
        CP_WAIT(0);
        __syncthreads();
        if (kt + 1 < nkt) issue_kv(kc + 64, stage ^ 1);
        const uint32_t kb = sb + ABUF0 + stage * KVBUF;

        // ---- S = Q K^T
        float s[8][4];
#pragma unroll
        for (int ni = 0; ni < 8; ni++)
#pragma unroll
            for (int r = 0; r < 4; r++) s[ni][r] = 0.f;
#pragma unroll
        for (int ks = 0; ks < 4; ks++) {
#pragma unroll
            for (int nip = 0; nip < 4; nip++) {
                uint32_t kf[4];
                uint32_t a = kb + (nip * 16 + (lane >> 4) * 8 + (lane & 7)) * KROWB
                           + ks * 32 + ((lane >> 3) & 1) * 16;
                ldsm_x4(kf, a);
                mma16816h(s[2 * nip],     qh[ks], kf);
                mma16816h(s[2 * nip + 1], qh[ks], kf + 2);
            }
        }

        // ---- mask (diagonal tile and/or SEQ boundary)
        if (kt == 0 || kc + 64 > SEQ) {
#pragma unroll
            for (int ni = 0; ni < 8; ni++)
#pragma unroll
                for (int r = 0; r < 4; r++) {
                    int key = kc + ni * 8 + 2 * (lane & 3) + (r & 1);
                    int qq  = qrow0 + (r >> 1) * 8;
                    if (key < qq || key >= SEQ) s[ni][r] = -FLT_MAX;
                }
        }

        // ---- online softmax
        float t0 = -FLT_MAX, t1 = -FLT_MAX;
#pragma unroll
        for (int ni = 0; ni < 8; ni++) {
            t0 = fmaxf(t0, fmaxf(s[ni][0], s[ni][1]));
            t1 = fmaxf(t1, fmaxf(s[ni][2], s[ni][3]));
        }
        t0 = fmaxf(t0, __shfl_xor_sync(0xffffffffu, t0, 1));
        t0 = fmaxf(t0, __shfl_xor_sync(0xffffffffu, t0, 2));
        t1 = fmaxf(t1, __shfl_xor_sync(0xffffffffu, t1, 1));
        t1 = fmaxf(t1, __shfl_xor_sync(0xffffffffu, t1, 2));
        float mn0 = fmaxf(m0, t0), mn1 = fmaxf(m1, t1);
        float c0 = __expf((m0 - mn0) * SCALE);
        float c1 = __expf((m1 - mn1) * SCALE);
        m0 = mn0; m1 = mn1;
        l0 *= c0;  l1 *= c1;
#pragma unroll
        for (int vi = 0; vi < 8; vi++) {
            o[vi][0] *= c0; o[vi][1] *= c0;
            o[vi][2] *= c1; o[vi][3] *= c1;
        }

        // ---- P = exp, pack fp16 a-fragments
        uint32_t pa[4][4];
#pragma unroll
        for (int ni = 0; ni < 8; ni++) {
            float p0 = __expf((s[ni][0] - m0) * SCALE);
            float p1 = __expf((s[ni][1] - m0) * SCALE);
            float p2 = __expf((s[ni][2] - m1) * SCALE);
            float p3 = __expf((s[ni][3] - m1) * SCALE);
            l0 += p0 + p1;  l1 += p2 + p3;
            int kj = ni >> 1;
            int rg = (ni & 1) * 2;
            pa[kj][rg]     = h2_bits(p0, p1);
            pa[kj][rg + 1] = h2_bits(p2, p3);
        }

        // ---- O += P V  (V frags via ldmatrix.trans)
#pragma unroll
        for (int kj = 0; kj < 4; kj++) {
#pragma unroll
            for (int vip = 0; vip < 4; vip++) {
                uint32_t vf[4];
                uint32_t a = kb + ATILEB
                           + (kj * 16 + ((lane >> 3) & 1) * 8 + (lane & 7)) * KROWB
                           + vip * 32 + (lane >> 4) * 16;
                ldsm_x4t(vf, a);
                mma16816h(o[2 * vip],     pa[kj], vf);
                mma16816h(o[2 * vip + 1], pa[kj], vf + 2);
            }
        }
    }

    // ---- epilogue
    l0 += __shfl_xor_sync(0xffffffffu, l0, 1);
    l0 += __shfl_xor_sync(0xffffffffu, l0, 2);
    l1 += __shfl_xor_sync(0xffffffffu, l1, 1);
    l1 += __shfl_xor_sync(0xffffffffu, l1, 2);
    float inv0 = 1.f / l0, inv1 = 1.f / l1;

    const int b = bh / NHEAD, h = bh - b * NHEAD;
#pragma unroll
    for (int half = 0; half < 2; half++) {
        int q = q0 + wid * 16 + (lane >> 2) + half * 8;
        if (q >= SEQ) continue;
        size_t rowb = ((size_t)(b * SEQ + q)) * DMODEL + h * HDIM;
        float inv = half ? inv1 : inv0;
#pragma unroll
        for (int vi = 0; vi < 8; vi++) {
            int d = vi * 8 + 2 * (lane & 3);
            *(uint32_t*)(g_ch + rowb + d) =
                h2_bits(o[vi][half * 2 + 0] * inv, o[vi][half * 2 + 1] * inv);
        }
    }
}

// ---------------------------------------------------------------------------
extern "C" void kernel_launch(void* const* d_in, const int* in_sizes, int n_in,
                              void* d_out, int out_size)
{
    (void)in_sizes; (void)n_in; (void)out_size;
    const float* x  = (const float*)d_in[0];
    const float* Wq = (const float*)d_in[1];
    const float* bq = (const float*)d_in[2];
    const float* Wk = (const float*)d_in[3];
    const float* bk = (const float*)d_in[4];
    const float* Wv = (const float*)d_in[5];
    const float* bv = (const float*)d_in[6];
    const float* Wo = (const float*)d_in[7];
    const float* bo = (const float*)d_in[8];
    float* out = (float*)d_out;

    cudaFuncSetAttribute(gemm_tc<1>, cudaFuncAttributeMaxDynamicSharedMemorySize, GEMM_SMEM);
    cudaFuncSetAttribute(gemm_tc<0>, cudaFuncAttributeMaxDynamicSharedMemorySize, GEMM_SMEM);
    cudaFuncSetAttribute(attn_mma,   cudaFuncAttributeMaxDynamicSharedMemorySize, ATT_SMEM);

    {
        int n4 = ELEMS / 4;
        to_fp16<<<(n4 + 255) / 256, 256>>>(x, 4, n4);
        int w4 = WSZ / 4;
        to_fp16<<<(w4 + 255) / 256, 256>>>(Wq, 0, w4);
        to_fp16<<<(w4 + 255) / 256, 256>>>(Wk, 1, w4);
        to_fp16<<<(w4 + 255) / 256, 256>>>(Wv, 2, w4);
        to_fp16<<<(w4 + 255) / 256, 256>>>(Wo, 3, w4);
    }

    // Fused QKV projection (18 n-tiles = 3 matrices x 6)
    gemm_tc<1><<<dim3(18, (MROWS + 127) / 128), 256, GEMM_SMEM>>>(bq, bk, bv, nullptr);

    // MMA flash attention
    attn_mma<<<dim3((SEQ + 63) / 64, BATCH * NHEAD), 128, ATT_SMEM>>>();

    // Output projection
    gemm_tc<0><<<dim3(6, (MROWS + 127) / 128), 256, GEMM_SMEM>>>(bo, nullptr, nullptr, out);
}